// round 15
// baseline (speedup 1.0000x reference)
#include <cuda_runtime.h>
#include <math.h>

// ---------------------------------------------------------------------------
// HistogramLoss on GB300 — transposed float2 gathers, GD=2 fused KDE.
//
// feature: [1, 64, 128, 128] fp32 ; label: [1, 1, 512, 512] int32 ; out: scalar
//
// Per class c, dim d:
//   miu = Σ w x / n,  var = Σ w x²/n - miu² + 1e-10
//   S[k] = Σ_q w[c,q] exp(-12.5 ((miu + k·std - x_q)/std)²),  k = -3..3
//   hist = S/ΣS, targ = const normalized gaussian, loss = mean smooth_l1
//
// Pipeline (counters statically zero; k_final re-zeros them for graph replay):
//   k_build_tr : blocks 0..127   : 4x4 label counts -> per-class packed lists
//                                  (block-aggregated atomic reservation)
//                blocks 128..1151: 32x32 tiled transpose feature -> [q][d]
//   k_fused    : one block per (d-pair, c), 512 threads (4 blocks/SM, 64
//                warps/SM, single wave): one pass -> float2 gather serves
//                both d's; register stats + 2 weighted x-histograms (3072
//                bins each, δ=1/256 over [-6,6)); KDE via gaussian
//                recurrence; smooth-l1 vs hardcoded target
//   k_final    : one warp per class, scalar reduce; re-zero counters
// ---------------------------------------------------------------------------

#define NUM_C  19
#define PC     16384            // 128*128 coarse pixels
#define DD     64
#define NBX    3072             // x-histogram bins over [-6, 6), delta = 1/256
#define HWF    1.30f            // gaussian half-window in std units

__device__ unsigned int g_list[NUM_C * PC];   // packed (q<<5)|w
__device__ int    g_cnt[NUM_C];               // entries per class  (zero-init)
__device__ int    g_n[NUM_C];                 // class totals       (zero-init)
__device__ float  g_partial[NUM_C * DD];      // per-(c,d) smooth-l1 sum
__device__ float2 g_xt[PC * (DD / 2)];        // transposed feature [q][d-pair]

// target histogram exp(-0.5 k^2)/sum, k=-3..3 (exact constants)
__constant__ float c_targ[7] = {
    0.00443305f, 0.05400557f, 0.24203623f, 0.39905027f,
    0.24203623f, 0.05400557f, 0.00443305f };

// ----------------------------------------------------- build + transpose ----
// blocks 0..127: one thread per coarse pixel; warp ballots -> smem per-warp
// counts -> warp0 lanes 0..18 do the block's single spread-address atomic
// reservation + intra-block prefix -> scatter entries.
// blocks 128..1151: 32x32 tiled transpose of feature into g_xt ([q][d]).
__global__ __launch_bounds__(128) void k_build_tr(const int* __restrict__ label,
                                                  const float* __restrict__ feat) {
    __shared__ unsigned short scnt[4][NUM_C];   // per-warp nonzero counts
    __shared__ unsigned short stot[4][NUM_C];   // per-warp weight totals
    __shared__ int   sbase[4][NUM_C];           // intra-block exclusive prefix
    __shared__ int   gbase[NUM_C];              // global segment base
    __shared__ float tile[32][33];

    int t = threadIdx.x;
    int lane = t & 31, wid = t >> 5;

    if (blockIdx.x >= 128) {
        // ---- transpose ----
        int tb = blockIdx.x - 128;              // 0..1023
        int q0 = (tb & 511) * 32;               // 512 q-tiles
        int d0 = (tb >> 9) * 32;                // 2 d-tiles
        for (int r = wid; r < 32; r += 4)
            tile[r][lane] = feat[(d0 + r) * PC + q0 + lane];
        __syncthreads();
        float* xtf = (float*)g_xt;
        for (int r = wid; r < 32; r += 4)
            xtf[(q0 + r) * DD + d0 + lane] = tile[lane][r];
        return;
    }

    // ---- build ----
    int q = blockIdx.x * 128 + t;           // 128 blocks * 128 = 16384
    int y = q >> 7, x = q & 127;
    const int4* lp = (const int4*)label;    // 512 ints per fine row = 128 int4
    int base = y * 512 + x;                 // int4 index of fine row 4y, col 4x

    int w[NUM_C];
    #pragma unroll
    for (int c = 0; c < NUM_C; c++) w[c] = 0;

    #pragma unroll
    for (int r = 0; r < 4; r++) {
        int4 v = lp[base + r * 128];
        #pragma unroll
        for (int c = 0; c < NUM_C; c++)
            w[c] += (v.x == c) + (v.y == c) + (v.z == c) + (v.w == c);
    }

    unsigned bal[NUM_C];
    #pragma unroll
    for (int c = 0; c < NUM_C; c++) {
        bal[c] = __ballot_sync(0xffffffffu, w[c] != 0);
        int tot = __reduce_add_sync(0xffffffffu, w[c]);
        if (lane == 0) {
            scnt[wid][c] = (unsigned short)__popc(bal[c]);
            stot[wid][c] = (unsigned short)tot;
        }
    }
    __syncthreads();

    if (wid == 0 && lane < NUM_C) {
        int run = 0, tt = 0;
        #pragma unroll
        for (int ww = 0; ww < 4; ww++) {
            sbase[ww][lane] = run;
            run += scnt[ww][lane];
            tt  += stot[ww][lane];
        }
        gbase[lane] = atomicAdd(&g_cnt[lane], run);
        if (tt) atomicAdd(&g_n[lane], tt);
    }
    __syncthreads();

    unsigned lmask = (1u << lane) - 1u;
    #pragma unroll
    for (int c = 0; c < NUM_C; c++) {
        if (w[c]) g_list[c * PC + gbase[c] + sbase[wid][c] + __popc(bal[c] & lmask)] =
                      ((unsigned)q << 5) | (unsigned)w[c];
    }
}

// --------------------------------------------------------------- fused ----
// One block per (d-pair dg, class c), 512 threads. Single pass over the
// compact list: one float2 gather per entry feeds exact register stats and
// two weighted x-histograms. Then per-d KDE + smooth-l1.
__global__ __launch_bounds__(512) void k_fused() {
    int dg = blockIdx.x, c = blockIdx.y;
    int t = threadIdx.x;
    int lane = t & 31, wid = t >> 5;

    __shared__ float H[2 * NBX];          // 24 KB
    __shared__ float S7[2][7];
    __shared__ float r1[16][2], r2[16][2];
    __shared__ float s_par[2][4];         // per d: A, jb0, std_bins, halfwin

    for (int i = t; i < 2 * NBX; i += 512) H[i] = 0.f;
    __syncthreads();

    int nnz = g_cnt[c];
    const unsigned int* __restrict__ list = g_list + c * PC;
    const float2* __restrict__ xt = g_xt + dg;   // entry q -> xt[q*32]

    // ---- single data pass: stats + two histograms, one gather ----
    float s1a = 0.f, s2a = 0.f, s1b = 0.f, s2b = 0.f;
    #pragma unroll 8
    for (int i = t; i < nnz; i += 512) {
        unsigned e = list[i];
        float w  = (float)(e & 31u);
        float2 xv = xt[(e >> 5) * (DD / 2)];
        float wxa = w * xv.x;
        s1a += wxa;
        s2a = fmaf(wxa, xv.x, s2a);
        float jfa = fmaf(xv.x, 256.f, 1536.f);       // (x+6)*256
        jfa = fminf(fmaxf(jfa, 0.f), (float)(NBX - 1));
        atomicAdd(&H[(int)jfa], w);                  // integer adds: exact
        float wxb = w * xv.y;
        s1b += wxb;
        s2b = fmaf(wxb, xv.y, s2b);
        float jfb = fmaf(xv.y, 256.f, 1536.f);
        jfb = fminf(fmaxf(jfb, 0.f), (float)(NBX - 1));
        atomicAdd(&H[NBX + (int)jfb], w);
    }
    #pragma unroll
    for (int o = 16; o; o >>= 1) {
        s1a += __shfl_down_sync(0xffffffffu, s1a, o);
        s2a += __shfl_down_sync(0xffffffffu, s2a, o);
        s1b += __shfl_down_sync(0xffffffffu, s1b, o);
        s2b += __shfl_down_sync(0xffffffffu, s2b, o);
    }
    if (lane == 0) {
        r1[wid][0] = s1a; r2[wid][0] = s2a;
        r1[wid][1] = s1b; r2[wid][1] = s2b;
    }
    __syncthreads();
    if (t < 2) {
        float a = 0.f, b = 0.f;
        #pragma unroll
        for (int i = 0; i < 16; i++) { a += r1[i][t]; b += r2[i][t]; }
        float n   = (float)g_n[c];
        float ns  = fmaxf(n, 1.0f);
        float miu = a / ns;
        float var = b / ns - miu * miu + 1e-10f;
        var = fmaxf(var, 1e-10f);
        float std = sqrtf(var);
        s_par[t][0] = 12.5f / (var * 65536.0f);       // A (bin units)
        s_par[t][1] = fmaf(miu, 256.f, 1535.5f);      // jb0: bin coord of miu
        s_par[t][2] = std * 256.0f;                   // std in bins
        s_par[t][3] = HWF * std * 256.0f;             // half window in bins
    }
    __syncthreads();

    // ---- KDE: 14 warp-tasks (2 d x 7 bins) over 16 warps ----
    if (wid < 14) {
        int dloc = wid / 7;
        int k    = wid - dloc * 7 - 3;
        float A  = s_par[dloc][0];
        float jb = fmaf((float)k, s_par[dloc][2], s_par[dloc][1]);
        float hw = s_par[dloc][3];
        int jlo = max(0,        (int)ceilf(jb - hw));
        int jhi = min(NBX - 1,  (int)floorf(jb + hw));
        const float* Hd = H + dloc * NBX;
        float acc = 0.f;
        int j = jlo + lane;
        if (j <= jhi) {
            float dd  = (float)j - jb;
            float e   = __expf(-A * dd * dd);
            float r   = __expf(-A * fmaf(64.f, dd, 1024.f));   // ratio j -> j+32
            float c32 = __expf(-2048.f * A);                   // ratio update
            for (; j <= jhi; j += 32) {
                acc = fmaf(e, Hd[j], acc);
                e *= r;
                r *= c32;
            }
        }
        #pragma unroll
        for (int o = 16; o; o >>= 1) acc += __shfl_down_sync(0xffffffffu, acc, o);
        if (lane == 0) S7[dloc][k + 3] = acc;
    }
    __syncthreads();

    if (t < 2) {
        float tot = 0.f;
        #pragma unroll
        for (int k = 0; k < 7; k++) tot += S7[t][k];
        float inv = 1.0f / fmaxf(tot, 1e-30f);
        float ls = 0.f;
        #pragma unroll
        for (int k = 0; k < 7; k++) {
            float dlt = S7[t][k] * inv - c_targ[k];
            float aa = fabsf(dlt);
            ls += (aa < 1.f) ? 0.5f * aa * aa : aa - 0.5f;
        }
        g_partial[c * DD + dg * 2 + t] = ls;
    }
}

// --------------------------------------------------------------- final ----
// One warp per class; then re-zero counters so the next graph replay starts
// from clean state (statically zero on the very first run).
__global__ void k_final(float* __restrict__ out) {
    int t = threadIdx.x;
    int lane = t & 31, c = t >> 5;            // 19 warps
    __shared__ float sl[NUM_C], sa[NUM_C];
    float s = g_partial[c * DD + lane] + g_partial[c * DD + 32 + lane];
    #pragma unroll
    for (int o = 16; o; o >>= 1) s += __shfl_down_sync(0xffffffffu, s, o);
    if (lane == 0) {
        float act = (g_n[c] >= 1000) ? 1.f : 0.f;
        sl[c] = s * (1.0f / 448.0f) * act;    // mean over 64*7 elements, masked
        sa[c] = act;
    }
    __syncthreads();
    if (t < NUM_C) { g_cnt[t] = 0; g_n[t] = 0; }   // reset for next replay
    if (t == 0) {
        float L = 0.f, A = 0.f;
        #pragma unroll
        for (int cc = 0; cc < NUM_C; cc++) { L += sl[cc]; A += sa[cc]; }
        out[0] = L / A;
    }
}

// -------------------------------------------------------------- launch ----
extern "C" void kernel_launch(void* const* d_in, const int* in_sizes, int n_in,
                              void* d_out, int out_size) {
    const float* feat  = (const float*)d_in[0];
    const int*   label = (const int*)d_in[1];
    // robustness: identify inputs by element count (feature=1048576, label=262144)
    if (n_in >= 2 && in_sizes[0] == 262144) {
        feat  = (const float*)d_in[1];
        label = (const int*)d_in[0];
    }

    k_build_tr<<<128 + 1024, 128>>>(label, feat);
    dim3 g(DD / 2, NUM_C);
    k_fused<<<g, 512>>>();
    k_final<<<1, NUM_C * 32>>>((float*)d_out);
}

// round 16
// speedup vs baseline: 1.2339x; 1.2339x over previous
#include <cuda_runtime.h>
#include <math.h>

// ---------------------------------------------------------------------------
// HistogramLoss on GB300 — 2-launch pipeline, x-histogram KDE.
//
// feature: [1, 64, 128, 128] fp32 ; label: [1, 1, 512, 512] int32 ; out: scalar
//
// Per class c, dim d:
//   miu = Σ w x / n,  var = Σ w x²/n - miu² + 1e-10
//   S[k] = Σ_q w[c,q] exp(-12.5 ((miu + k·std - x_q)/std)²),  k = -3..3
//   hist = S/ΣS, targ = const normalized gaussian, loss = mean smooth_l1
//
// Pipeline (counters statically zero; last k_fused block re-zeros them):
//   k_build : 64x256, per-pixel 4x4 label counts via nibble-packed u64
//             counters -> per-class packed lists (block-aggregated
//             spread-address atomic reservation).
//   k_fused : one block per (d, c), 256 thr: single pass (uint2 list loads,
//             dense-layout x gathers) -> register stats + weighted
//             x-histogram (3072 bins, δ=1/256 over [-6,6)); KDE via
//             gaussian recurrence; smooth-l1; LAST block reduces to the
//             scalar output and resets counters (threadfence+ticket).
// ---------------------------------------------------------------------------

#define NUM_C  19
#define PC     16384            // 128*128 coarse pixels
#define DD     64
#define NBX    3072             // x-histogram bins over [-6, 6), delta = 1/256
#define HWF    1.30f            // gaussian half-window in std units
#define GRID_T (DD * NUM_C)     // 1216 fused blocks

__device__ unsigned int g_list[NUM_C * PC];   // packed (q<<5)|w
__device__ int      g_cnt[NUM_C];             // entries per class  (zero-init)
__device__ int      g_n[NUM_C];               // class totals       (zero-init)
__device__ float    g_partial[NUM_C * DD];    // per-(c,d) smooth-l1 sum
__device__ unsigned g_done;                   // completion ticket  (zero-init)

// target histogram exp(-0.5 k^2)/sum, k=-3..3 (exact constants)
__constant__ float c_targ[7] = {
    0.00443305f, 0.05400557f, 0.24203623f, 0.39905027f,
    0.24203623f, 0.05400557f, 0.00443305f };

// --------------------------------------------------------------- build ----
// 64 blocks x 256 threads, one thread per coarse pixel.
// Nibble-packed per-thread counting (5 bits/class across two u64), then
// warp ballots -> smem per-warp counts -> warp0 lanes 0..18 do the block's
// single spread-address atomic reservation + intra-block prefix -> scatter.
__global__ __launch_bounds__(256) void k_build(const int* __restrict__ label) {
    __shared__ unsigned short scnt[8][NUM_C];   // per-warp nonzero counts
    __shared__ unsigned short stot[8][NUM_C];   // per-warp weight totals
    __shared__ int   sbase[8][NUM_C];           // intra-block exclusive prefix
    __shared__ int   gbase[NUM_C];              // global segment base

    int t = threadIdx.x;
    int lane = t & 31, wid = t >> 5;
    int q = blockIdx.x * 256 + t;           // 64 blocks * 256 = 16384
    int y = q >> 7, x = q & 127;
    const int4* lp = (const int4*)label;    // 512 ints per fine row = 128 int4
    int base = y * 512 + x;                 // int4 index of fine row 4y, col 4x

    // packed counters: classes 0..11 in lo (5 bits each), 12..18 in hi
    unsigned long long lo = 0ull, hi = 0ull;
    #pragma unroll
    for (int r = 0; r < 4; r++) {
        int4 v = lp[base + r * 128];
        int cv[4] = { v.x, v.y, v.z, v.w };
        #pragma unroll
        for (int u = 0; u < 4; u++) {
            int c = cv[u];
            if (c < 12) lo += 1ull << (5 * c);
            else        hi += 1ull << (5 * (c - 12));
        }
    }
    int w[NUM_C];
    #pragma unroll
    for (int c = 0; c < 12; c++)    w[c] = (int)((lo >> (5 * c)) & 31ull);
    #pragma unroll
    for (int c = 12; c < NUM_C; c++) w[c] = (int)((hi >> (5 * (c - 12))) & 31ull);

    // per-warp ballots + counts into smem
    unsigned bal[NUM_C];
    #pragma unroll
    for (int c = 0; c < NUM_C; c++) {
        bal[c] = __ballot_sync(0xffffffffu, w[c] != 0);
        int tot = __reduce_add_sync(0xffffffffu, w[c]);
        if (lane == 0) {
            scnt[wid][c] = (unsigned short)__popc(bal[c]);
            stot[wid][c] = (unsigned short)tot;
        }
    }
    __syncthreads();

    // warp 0: lane c owns class c — prefix over 8 warps + ONE atomic each
    if (wid == 0 && lane < NUM_C) {
        int run = 0, tt = 0;
        #pragma unroll
        for (int ww = 0; ww < 8; ww++) {
            sbase[ww][lane] = run;
            run += scnt[ww][lane];
            tt  += stot[ww][lane];
        }
        gbase[lane] = atomicAdd(&g_cnt[lane], run);
        if (tt) atomicAdd(&g_n[lane], tt);
    }
    __syncthreads();

    // scatter entries
    unsigned lmask = (1u << lane) - 1u;
    #pragma unroll
    for (int c = 0; c < NUM_C; c++) {
        if (w[c]) g_list[c * PC + gbase[c] + sbase[wid][c] + __popc(bal[c] & lmask)] =
                      ((unsigned)q << 5) | (unsigned)w[c];
    }
}

// --------------------------------------------------------------- fused ----
// One block per (d, c), 256 threads: single pass over the compact list
// (uint2 = 2 entries per lane) accumulates exact register stats AND the
// weighted x-histogram; then KDE + smooth-l1. Last finishing block reduces
// g_partial to the scalar loss and resets counters for the next replay.
__global__ __launch_bounds__(256) void k_fused(const float* __restrict__ feat,
                                               float* __restrict__ out) {
    int d = blockIdx.x, c = blockIdx.y;
    int t = threadIdx.x;
    int lane = t & 31, wid = t >> 5;

    __shared__ float H[NBX];
    __shared__ float S7[7];
    __shared__ float r1[8], r2[8];
    __shared__ float s_par[4];     // A, jb0, std_bins, halfwin_bins
    __shared__ unsigned s_ticket;
    __shared__ float sl[NUM_C], sa[NUM_C];

    for (int i = t; i < NBX; i += 256) H[i] = 0.f;
    __syncthreads();

    int nnz = g_cnt[c];
    const unsigned int* __restrict__ list = g_list + c * PC;
    const uint2* __restrict__ list2 = (const uint2*)list;
    const float* __restrict__ xrow = feat + d * PC;

    // ---- single data pass: exact stats + weighted x-histogram ----
    float s1 = 0.f, s2 = 0.f;
    int npair = nnz >> 1;
    #pragma unroll 4
    for (int i = t; i < npair; i += 256) {
        uint2 ee = list2[i];
        float wa = (float)(ee.x & 31u);
        float xa = xrow[ee.x >> 5];
        float wb = (float)(ee.y & 31u);
        float xb = xrow[ee.y >> 5];
        float wxa = wa * xa;
        s1 += wxa;
        s2 = fmaf(wxa, xa, s2);
        float ja = fmaf(xa, 256.f, 1536.f);          // (x+6)*256
        ja = fminf(fmaxf(ja, 0.f), (float)(NBX - 1));
        atomicAdd(&H[(int)ja], wa);                  // integer adds: exact
        float wxb = wb * xb;
        s1 += wxb;
        s2 = fmaf(wxb, xb, s2);
        float jb = fmaf(xb, 256.f, 1536.f);
        jb = fminf(fmaxf(jb, 0.f), (float)(NBX - 1));
        atomicAdd(&H[(int)jb], wb);
    }
    if ((nnz & 1) && t == 0) {                        // odd tail
        unsigned e = list[nnz - 1];
        float w = (float)(e & 31u);
        float x = xrow[e >> 5];
        float wx = w * x;
        s1 += wx;
        s2 = fmaf(wx, x, s2);
        float jf = fmaf(x, 256.f, 1536.f);
        jf = fminf(fmaxf(jf, 0.f), (float)(NBX - 1));
        atomicAdd(&H[(int)jf], w);
    }
    #pragma unroll
    for (int o = 16; o; o >>= 1) {
        s1 += __shfl_down_sync(0xffffffffu, s1, o);
        s2 += __shfl_down_sync(0xffffffffu, s2, o);
    }
    if (lane == 0) { r1[wid] = s1; r2[wid] = s2; }
    __syncthreads();
    if (t == 0) {
        float a = 0.f, b = 0.f;
        #pragma unroll
        for (int i = 0; i < 8; i++) { a += r1[i]; b += r2[i]; }
        float n   = (float)g_n[c];
        float ns  = fmaxf(n, 1.0f);
        float miu = a / ns;
        float var = b / ns - miu * miu + 1e-10f;
        var = fmaxf(var, 1e-10f);
        float std = sqrtf(var);
        s_par[0] = 12.5f / (var * 65536.0f);          // A (bin units)
        s_par[1] = fmaf(miu, 256.f, 1535.5f);         // jb0: bin coord of miu
        s_par[2] = std * 256.0f;                      // std in bins
        s_par[3] = HWF * std * 256.0f;                // half window in bins
    }
    __syncthreads();

    // ---- 7-bin KDE: warp wid handles k = wid-3 ----
    if (wid < 7) {
        float A  = s_par[0];
        float jb = fmaf((float)(wid - 3), s_par[2], s_par[1]);
        float hw = s_par[3];
        int jlo = max(0,        (int)ceilf(jb - hw));
        int jhi = min(NBX - 1,  (int)floorf(jb + hw));
        float acc = 0.f;
        int j = jlo + lane;
        if (j <= jhi) {
            float dd  = (float)j - jb;
            float e   = __expf(-A * dd * dd);
            float r   = __expf(-A * fmaf(64.f, dd, 1024.f));   // ratio j -> j+32
            float c32 = __expf(-2048.f * A);                   // ratio update
            for (; j <= jhi; j += 32) {
                acc = fmaf(e, H[j], acc);
                e *= r;
                r *= c32;
            }
        }
        #pragma unroll
        for (int o = 16; o; o >>= 1) acc += __shfl_down_sync(0xffffffffu, acc, o);
        if (lane == 0) S7[wid] = acc;
    }
    __syncthreads();

    if (t == 0) {
        float tot = 0.f;
        #pragma unroll
        for (int k = 0; k < 7; k++) tot += S7[k];
        float inv = 1.0f / fmaxf(tot, 1e-30f);
        float ls = 0.f;
        #pragma unroll
        for (int k = 0; k < 7; k++) {
            float dlt = S7[k] * inv - c_targ[k];
            float aa = fabsf(dlt);
            ls += (aa < 1.f) ? 0.5f * aa * aa : aa - 0.5f;
        }
        g_partial[c * DD + d] = ls;
        __threadfence();                           // publish before ticket
        s_ticket = atomicAdd(&g_done, 1u);
    }
    __syncthreads();

    // ---- last block: final reduction + counter reset ----
    if (s_ticket == GRID_T - 1) {
        for (int cc = wid; cc < NUM_C; cc += 8) {
            float s = g_partial[cc * DD + lane] + g_partial[cc * DD + 32 + lane];
            #pragma unroll
            for (int o = 16; o; o >>= 1) s += __shfl_down_sync(0xffffffffu, s, o);
            if (lane == 0) {
                float act = (g_n[cc] >= 1000) ? 1.f : 0.f;
                sl[cc] = s * (1.0f / 448.0f) * act;   // mean over 64*7, masked
                sa[cc] = act;
            }
        }
        __syncthreads();
        if (t < NUM_C) { g_cnt[t] = 0; g_n[t] = 0; }  // reset for next replay
        if (t == 0) {
            g_done = 0;
            float L = 0.f, A = 0.f;
            #pragma unroll
            for (int cc = 0; cc < NUM_C; cc++) { L += sl[cc]; A += sa[cc]; }
            out[0] = L / A;
        }
    }
}

// -------------------------------------------------------------- launch ----
extern "C" void kernel_launch(void* const* d_in, const int* in_sizes, int n_in,
                              void* d_out, int out_size) {
    const float* feat  = (const float*)d_in[0];
    const int*   label = (const int*)d_in[1];
    // robustness: identify inputs by element count (feature=1048576, label=262144)
    if (n_in >= 2 && in_sizes[0] == 262144) {
        feat  = (const float*)d_in[1];
        label = (const int*)d_in[0];
    }

    k_build<<<64, 256>>>(label);
    dim3 g(DD, NUM_C);
    k_fused<<<g, 256>>>(feat, (float*)d_out);
}